// round 2
// baseline (speedup 1.0000x reference)
#include <cuda_runtime.h>

// GaussianPooling: out[n,c] = sum_{dy,dx} fm[c, y+dy, x+dx] * kern[dy,dx]
// fm: [512, 256, 256] f32, keypoints: [4096, 2] integer (x, y), out: [4096, 512] f32
// kern is a normalized 5x5 Gaussian (sigma=2), which is separable.

#define C_DIM 512
#define H_DIM 256
#define W_DIM 256
#define N_KP  4096
#define PLANE (H_DIM * W_DIM)

// nonzero => keypoints buffer is int32 pairs; zero => int64 pairs
__device__ int g_kp_is_i32;

static __device__ __forceinline__ float gval(float i) {
    float d = i - 2.0f;
    return __expf(-d * d * 0.125f);   // exp(-d^2 / (2*sigma^2)), sigma=2
}

// One block. ORs all odd int32 elements of the keypoint buffer.
// int64 data (little-endian): odd elements are high words == 0 -> flag 0.
// int32 data: odd elements are y coords (random in [0,256)) -> flag != 0.
__global__ void detect_kp_dtype(const int* __restrict__ kp32, int n_elems)
{
    __shared__ int s_or[256];
    int acc = 0;
    for (int i = 1 + 2 * threadIdx.x; i < n_elems; i += 2 * blockDim.x)
        acc |= kp32[i];
    s_or[threadIdx.x] = acc;
    __syncthreads();
    for (int s = 128; s > 0; s >>= 1) {
        if (threadIdx.x < s) s_or[threadIdx.x] |= s_or[threadIdx.x + s];
        __syncthreads();
    }
    if (threadIdx.x == 0) g_kp_is_i32 = s_or[0];
}

__global__ void __launch_bounds__(256)
gauss_pool_kernel(const float* __restrict__ fm,
                  const int* __restrict__ kp32,
                  float* __restrict__ out)
{
    const int n   = blockIdx.x;
    const int tid = threadIdx.x;

    int x, y;
    if (g_kp_is_i32) {           // int32 pairs: [x, y] at 2n
        x = kp32[2 * n + 0];
        y = kp32[2 * n + 1];
    } else {                      // int64 pairs: low words at 4n and 4n+2
        x = kp32[4 * n + 0];
        y = kp32[4 * n + 2];
    }
    // clip like the reference: [HALF_K, dim - HALF_K - 1]
    x = min(max(x, 2), W_DIM - 3);
    y = min(max(y, 2), H_DIM - 3);

    const int w0  = x - 2;          // leftmost column of the 5-wide window
    const int a   = w0 & ~3;        // float4-aligned base (a <= w0 <= a+3)
    const int off = w0 - a;         // 0..3, uniform across the block

    // normalized 1D gaussian weights (separable: kern = outer(g,g)/sum(k))
    const float inv_norm =
        1.0f / (gval(0.f) + gval(1.f) + gval(2.f) + gval(3.f) + gval(4.f));

    float gy[5];
    #pragma unroll
    for (int r = 0; r < 5; ++r) gy[r] = gval((float)r) * inv_norm;

    // shifted horizontal weights over the aligned 8-float window:
    // gx[j] = g[j - off] for j in [off, off+5), else 0
    __shared__ float s_gx[8];
    if (tid < 8) {
        int i = tid - off;
        s_gx[tid] = (i >= 0 && i < 5) ? gval((float)i) * inv_norm : 0.0f;
    }
    __syncthreads();

    float gx[8];
    #pragma unroll
    for (int j = 0; j < 8; ++j) gx[j] = s_gx[j];

    const float* pbase = fm + (y - 2) * W_DIM + a;

    // 256 threads x 2 channels each = 512 channels
    #pragma unroll
    for (int cc = 0; cc < 2; ++cc) {
        const int c = tid + cc * 256;
        const float* p = pbase + (size_t)c * PLANE;

        // issue all 10 LDG.128 up front for MLP
        float4 A[5], B[5];
        #pragma unroll
        for (int r = 0; r < 5; ++r) {
            A[r] = *(const float4*)(p + r * W_DIM);
            B[r] = *(const float4*)(p + r * W_DIM + 4);
        }

        float acc = 0.0f;
        #pragma unroll
        for (int r = 0; r < 5; ++r) {
            float rs = gx[0] * A[r].x + gx[1] * A[r].y
                     + gx[2] * A[r].z + gx[3] * A[r].w
                     + gx[4] * B[r].x + gx[5] * B[r].y
                     + gx[6] * B[r].z + gx[7] * B[r].w;
            acc = fmaf(gy[r], rs, acc);
        }

        out[n * C_DIM + c] = acc;
    }
}

extern "C" void kernel_launch(void* const* d_in, const int* in_sizes, int n_in,
                              void* d_out, int out_size)
{
    const float* fm   = (const float*)d_in[0];   // [512,256,256] f32
    const int*   kp32 = (const int*)d_in[1];     // [4096,2] int32 or int64 (detected)
    float*       out  = (float*)d_out;           // [4096,512] f32

    // element count of the keypoint buffer viewed as int32:
    // if in_sizes[1] counts int64 elements (8192), the int32 view has 16384;
    // scanning 2*in_sizes[1] odd slots is safe for the int32 case too only if
    // the buffer really has that many int32s -> use the smaller safe bound.
    // For int32 data: 8192 int32s. For int64 data: 16384 int32s. Scanning the
    // first 8192 int32 elements works for both (covers 2048 keypoints' worth
    // of odd slots for int64, 4096 y-coords for int32).
    detect_kp_dtype<<<1, 256>>>(kp32, 8192);
    gauss_pool_kernel<<<N_KP, 256>>>(fm, kp32, out);
}